// round 13
// baseline (speedup 1.0000x reference)
#include <cuda_runtime.h>

typedef unsigned int u32;
typedef unsigned short u16;

#define BB 4
#define SS 4096
#define DIN 1024
#define DH 64
#define MROWS (BB*SS)
#define NSPLIT 8
#define KTS (SS/64)
#define KT_PER (KTS/NSPLIT)

// ---------------- scratch (static device memory; no allocations) ----------
__device__ u16 g_Wth[3][DH*DIN], g_Wtl[3][DH*DIN];         // W^T split bf16 [out][din]
__device__ u16 g_Qh[MROWS*DH], g_Ql[MROWS*DH];             // [row][d]
__device__ u16 g_Kh[MROWS*DH], g_Kl[MROWS*DH];             // [row][d]
__device__ u16 g_Vh[MROWS*DH], g_Vl[MROWS*DH];             // transposed [b][d][s]
__device__ float g_Op[NSPLIT][MROWS*DH];                   // unnormalized partial O
__device__ float g_m[NSPLIT][MROWS];
__device__ float g_l[NSPLIT][MROWS];

// ---------------- helpers --------------------------------------------------
__device__ __forceinline__ u32 packbf(float lo, float hi){
    u32 r; asm("cvt.rn.bf16x2.f32 %0, %1, %2;" : "=r"(r) : "f"(hi), "f"(lo)); return r;
}
__device__ __forceinline__ float bflo(u32 p){ return __uint_as_float(p << 16); }
__device__ __forceinline__ float bfhi(u32 p){ return __uint_as_float(p & 0xffff0000u); }
__device__ __forceinline__ u32 smaddr(const void* p){ return (u32)__cvta_generic_to_shared(p); }

__device__ __forceinline__ void ldsm4(u32& r0,u32& r1,u32& r2,u32& r3, u32 a){
    asm volatile("ldmatrix.sync.aligned.m8n8.x4.shared.b16 {%0,%1,%2,%3}, [%4];"
        : "=r"(r0),"=r"(r1),"=r"(r2),"=r"(r3) : "r"(a));
}
__device__ __forceinline__ void mma_bf(float* c, const u32* a, u32 b0, u32 b1){
    asm volatile("mma.sync.aligned.m16n8k16.row.col.f32.bf16.bf16.f32 "
        "{%0,%1,%2,%3},{%4,%5,%6,%7},{%8,%9},{%0,%1,%2,%3};"
        : "+f"(c[0]),"+f"(c[1]),"+f"(c[2]),"+f"(c[3])
        : "r"(a[0]),"r"(a[1]),"r"(a[2]),"r"(a[3]),"r"(b0),"r"(b1));
}
__device__ __forceinline__ void cpa16(u32 dst, const void* src){
    asm volatile("cp.async.cg.shared.global [%0], [%1], 16;" :: "r"(dst), "l"(src));
}
#define CP_COMMIT() asm volatile("cp.async.commit_group;")
#define CP_WAIT1()  asm volatile("cp.async.wait_group 1;")

// ---------------- kernel: convert+transpose weights ------------------------
__global__ __launch_bounds__(256) void cvt_w(const float* __restrict__ Wq,
                                             const float* __restrict__ Wk,
                                             const float* __restrict__ Wv){
    int id = blockIdx.x*256 + threadIdx.x;
    int w = id >> 16; int r = id & 65535;
    int n = r >> 10, k = r & 1023;
    const float* W = (w==0) ? Wq : (w==1) ? Wk : Wv;
    float x = W[k*DH + n];
    u32 p = packbf(x, 0.f);
    u32 q = packbf(x - bflo(p), 0.f);
    g_Wth[w][n*DIN + k] = (u16)(p & 0xffff);
    g_Wtl[w][n*DIN + k] = (u16)(q & 0xffff);
}

__device__ __forceinline__ void storeV(int r, int c, float v){
    int bb = r >> 12, s = r & 4095;
    u32 p = packbf(v, 0.f);
    g_Vh[(size_t)(bb*64 + c)*SS + s] = (u16)(p & 0xffff);
    u32 q = packbf(v - bflo(p), 0.f);
    g_Vl[(size_t)(bb*64 + c)*SS + s] = (u16)(q & 0xffff);
}

// ---------------- kernel: QKV projection via HMMA, fused X split -----------
// grid (MROWS/128, 3), 128 threads. 4 warps x 2 x m16 groups = 128 rows/CTA.
__global__ __launch_bounds__(128, 3) void qkv_mma(
    const float* __restrict__ X,
    const float* __restrict__ bq, const float* __restrict__ bk,
    const float* __restrict__ bv)
{
    extern __shared__ u16 smq[];
    u16* Xs_h = smq;               // 128*72
    u16* Xs_l = Xs_h + 128*72;
    u16* Ws_h = Xs_l + 128*72;     // 64*72
    u16* Ws_l = Ws_h + 64*72;

    const int t = threadIdx.x, lane = t & 31, warp = t >> 5;
    const int w = blockIdx.y;
    const int m0 = blockIdx.x * 128;
    const u16* Wth = g_Wth[w]; const u16* Wtl = g_Wtl[w];
    const float* bias = (w==0) ? bq : (w==1) ? bk : bv;

    u32 a_h[2], a_l[2];
    #pragma unroll
    for (int grp = 0; grp < 2; grp++){
        u32 aoff = ((u32)(32*warp + 16*grp + (lane&15))*72 + ((lane>>4)<<3)) * 2;
        a_h[grp] = smaddr(Xs_h) + aoff;
        a_l[grp] = smaddr(Xs_l) + aoff;
    }
    const u32 boff = (((lane&7) + ((lane>>4)<<3))*72 + (((lane>>3)&1)<<3)) * 2;
    const u32 b_h = smaddr(Ws_h) + boff, b_l = smaddr(Ws_l) + boff;

    float acc[2][8][4] = {};
    for (int c16 = 0; c16 < 16; c16++){
        __syncthreads();
        #pragma unroll
        for (int u = 0; u < 8; u++){
            int idx = t + 128*u; int row = idx >> 3, q4 = idx & 7;
            const float* xp = &X[(size_t)(m0+row)*DIN + c16*64 + q4*8];
            float4 v0 = *(const float4*)xp;
            float4 v1 = *(const float4*)(xp + 4);
            u32 h01 = packbf(v0.x, v0.y), h23 = packbf(v0.z, v0.w);
            u32 h45 = packbf(v1.x, v1.y), h67 = packbf(v1.z, v1.w);
            u32 l01 = packbf(v0.x - bflo(h01), v0.y - bfhi(h01));
            u32 l23 = packbf(v0.z - bflo(h23), v0.w - bfhi(h23));
            u32 l45 = packbf(v1.x - bflo(h45), v1.y - bfhi(h45));
            u32 l67 = packbf(v1.z - bflo(h67), v1.w - bfhi(h67));
            *(uint4*)&Xs_h[row*72 + q4*8] = make_uint4(h01, h23, h45, h67);
            *(uint4*)&Xs_l[row*72 + q4*8] = make_uint4(l01, l23, l45, l67);
        }
        #pragma unroll
        for (int u = 0; u < 4; u++){
            int idx = t + 128*u; int row = idx >> 3, q4 = idx & 7;
            *(uint4*)&Ws_h[row*72 + q4*8] = *(const uint4*)&Wth[(size_t)row*DIN + c16*64 + q4*8];
            *(uint4*)&Ws_l[row*72 + q4*8] = *(const uint4*)&Wtl[(size_t)row*DIN + c16*64 + q4*8];
        }
        __syncthreads();
        #pragma unroll
        for (int ks = 0; ks < 4; ks++){
            u32 ah[2][4], al[2][4];
            #pragma unroll
            for (int grp = 0; grp < 2; grp++){
                ldsm4(ah[grp][0],ah[grp][1],ah[grp][2],ah[grp][3], a_h[grp] + ks*32);
                ldsm4(al[grp][0],al[grp][1],al[grp][2],al[grp][3], a_l[grp] + ks*32);
            }
            #pragma unroll
            for (int ph = 0; ph < 2; ph++){
                u32 b0h[4], b1h[4], b0l[4], b1l[4];
                ldsm4(b0h[0],b0h[1],b0h[2],b0h[3], b_h + (2*ph)*2304   + ks*32);
                ldsm4(b1h[0],b1h[1],b1h[2],b1h[3], b_h + (2*ph+1)*2304 + ks*32);
                ldsm4(b0l[0],b0l[1],b0l[2],b0l[3], b_l + (2*ph)*2304   + ks*32);
                ldsm4(b1l[0],b1l[1],b1l[2],b1l[3], b_l + (2*ph+1)*2304 + ks*32);
                #pragma unroll
                for (int grp = 0; grp < 2; grp++){
                    mma_bf(acc[grp][4*ph+0], ah[grp], b0h[0], b0h[1]);
                    mma_bf(acc[grp][4*ph+1], ah[grp], b0h[2], b0h[3]);
                    mma_bf(acc[grp][4*ph+2], ah[grp], b1h[0], b1h[1]);
                    mma_bf(acc[grp][4*ph+3], ah[grp], b1h[2], b1h[3]);
                    mma_bf(acc[grp][4*ph+0], ah[grp], b0l[0], b0l[1]);
                    mma_bf(acc[grp][4*ph+1], ah[grp], b0l[2], b0l[3]);
                    mma_bf(acc[grp][4*ph+2], ah[grp], b1l[0], b1l[1]);
                    mma_bf(acc[grp][4*ph+3], ah[grp], b1l[2], b1l[3]);
                    mma_bf(acc[grp][4*ph+0], al[grp], b0h[0], b0h[1]);
                    mma_bf(acc[grp][4*ph+1], al[grp], b0h[2], b0h[3]);
                    mma_bf(acc[grp][4*ph+2], al[grp], b1h[0], b1h[1]);
                    mma_bf(acc[grp][4*ph+3], al[grp], b1h[2], b1h[3]);
                }
            }
        }
    }

    const int g = lane >> 2, t2 = lane & 3;
    #pragma unroll
    for (int grp = 0; grp < 2; grp++){
        const int r0 = m0 + 32*warp + 16*grp + g, r1 = r0 + 8;
        #pragma unroll
        for (int nb = 0; nb < 8; nb++){
            int col = nb*8 + t2*2;
            float b0v = bias[col], b1v = bias[col+1];
            float v00 = fmaxf(acc[grp][nb][0] + b0v, 0.f);
            float v01 = fmaxf(acc[grp][nb][1] + b1v, 0.f);
            float v10 = fmaxf(acc[grp][nb][2] + b0v, 0.f);
            float v11 = fmaxf(acc[grp][nb][3] + b1v, 0.f);
            if (w == 2){
                storeV(r0, col, v00); storeV(r0, col+1, v01);
                storeV(r1, col, v10); storeV(r1, col+1, v11);
            } else {
                u16* Oh = (w==0) ? g_Qh : g_Kh;
                u16* Ol = (w==0) ? g_Ql : g_Kl;
                u32 h = packbf(v00, v01);
                u32 lo = packbf(v00 - bflo(h), v01 - bfhi(h));
                *(u32*)&Oh[(size_t)r0*DH + col] = h; *(u32*)&Ol[(size_t)r0*DH + col] = lo;
                h = packbf(v10, v11);
                lo = packbf(v10 - bflo(h), v11 - bfhi(h));
                *(u32*)&Oh[(size_t)r1*DH + col] = h; *(u32*)&Ol[(size_t)r1*DH + col] = lo;
            }
        }
    }
}

// ---------------- kernel: flash attention, double-buffered cp.async KV -----
// grid (SS/128, BB, NSPLIT), 128 threads. Bq=128 (4 warps x 32 rows), Bk=64.
// KV staged via cp.async into 2 buffers; compute math identical to R11.
#define KVW 4608            // u16 elements per KV array (64*72)
#define KVBUFU (4*KVW)      // u16 elements per KV buffer
__global__ __launch_bounds__(128, 2) void attn_mma()
{
    extern __shared__ u16 smu[];
    u16* Qh  = smu;                 // 128*72
    u16* Ql  = Qh + 128*72;
    u16* KV0 = Ql + 128*72;         // 2 x [Kh|Kl|Vh|Vl], each 64*72

    const int t = threadIdx.x, lane = t & 31, wid = t >> 5;
    const int b = blockIdx.y, z = blockIdx.z;
    const int q0 = blockIdx.x * 128;
    const int base = b * SS;

    // stage Q (128 rows, hi+lo)
    #pragma unroll
    for (int u = 0; u < 8; u++){
        int idx = t + 128*u; int row = idx >> 3, q4 = idx & 7;
        *(uint4*)&Qh[row*72 + q4*8] = *(const uint4*)&g_Qh[(size_t)(base+q0+row)*DH + q4*8];
        *(uint4*)&Ql[row*72 + q4*8] = *(const uint4*)&g_Ql[(size_t)(base+q0+row)*DH + q4*8];
    }

    u32 qh_a[2], ql_a[2];
    #pragma unroll
    for (int grp = 0; grp < 2; grp++){
        u32 aoff = ((u32)(32*wid + 16*grp + (lane&15))*72 + ((lane>>4)<<3)) * 2;
        qh_a[grp] = smaddr(Qh) + aoff;
        ql_a[grp] = smaddr(Ql) + aoff;
    }
    const u32 boff = (((lane&7) + ((lane>>4)<<3))*72 + (((lane>>3)&1)<<3)) * 2;
    const u32 kv_base = smaddr(KV0);

    // cp.async staging of tile tt into buffer s
    const int srow = t >> 1, sc4 = (t & 1) * 4;    // 64 rows, 2 threads/row
    auto stage = [&](int tt, int s){
        const int k0 = (z*KT_PER + tt) * 64;
        const u32 dst = kv_base + (u32)s * (KVBUFU*2);
        #pragma unroll
        for (int h = 0; h < 4; h++){
            int c = sc4 + h;                        // 16B chunk 0..7
            u32 doff = (srow*72 + c*8) * 2;
            const size_t gk = (size_t)(base+k0+srow)*DH + c*8;
            const size_t gv = (size_t)(b*64+srow)*SS + k0 + c*8;
            cpa16(dst + doff,            &g_Kh[gk]);
            cpa16(dst + KVW*2 + doff,    &g_Kl[gk]);
            cpa16(dst + 2*KVW*2 + doff,  &g_Vh[gv]);
            cpa16(dst + 3*KVW*2 + doff,  &g_Vl[gv]);
        }
    };

    stage(0, 0); CP_COMMIT();
    if (KT_PER > 1){ stage(1, 1); } CP_COMMIT();

    float o[2][8][4] = {};
    float mr[2][2] = {{-3e38f,-3e38f},{-3e38f,-3e38f}};
    float lr[2][2] = {{0.f,0.f},{0.f,0.f}};

    for (int it = 0; it < KT_PER; it++){
        CP_WAIT1();                 // tile it complete (tile it+1 may be in flight)
        __syncthreads();            // data visible + all warps past prior compute

        const u32 st   = kv_base + (u32)(it & 1) * (KVBUFU*2);
        const u32 kh_b = st + boff;
        const u32 kl_b = st + KVW*2 + boff;
        const u32 vh_b = st + 2*KVW*2 + boff;
        const u32 vl_b = st + 3*KVW*2 + boff;

        // ---- S = Q @ K^T (full 3-product split) ----
        float s[2][8][4] = {};
        #pragma unroll
        for (int ks = 0; ks < 4; ks++){
            u32 ah[2][4], al[2][4];
            #pragma unroll
            for (int grp = 0; grp < 2; grp++){
                ldsm4(ah[grp][0],ah[grp][1],ah[grp][2],ah[grp][3], qh_a[grp] + ks*32);
                ldsm4(al[grp][0],al[grp][1],al[grp][2],al[grp][3], ql_a[grp] + ks*32);
            }
            #pragma unroll
            for (int ph = 0; ph < 2; ph++){
                u32 b0h[4], b1h[4], b0l[4], b1l[4];
                ldsm4(b0h[0],b0h[1],b0h[2],b0h[3], kh_b + (2*ph)*2304   + ks*32);
                ldsm4(b1h[0],b1h[1],b1h[2],b1h[3], kh_b + (2*ph+1)*2304 + ks*32);
                ldsm4(b0l[0],b0l[1],b0l[2],b0l[3], kl_b + (2*ph)*2304   + ks*32);
                ldsm4(b1l[0],b1l[1],b1l[2],b1l[3], kl_b + (2*ph+1)*2304 + ks*32);
                #pragma unroll
                for (int grp = 0; grp < 2; grp++){
                    mma_bf(s[grp][4*ph+0], ah[grp], b0h[0], b0h[1]);
                    mma_bf(s[grp][4*ph+1], ah[grp], b0h[2], b0h[3]);
                    mma_bf(s[grp][4*ph+2], ah[grp], b1h[0], b1h[1]);
                    mma_bf(s[grp][4*ph+3], ah[grp], b1h[2], b1h[3]);
                    mma_bf(s[grp][4*ph+0], ah[grp], b0l[0], b0l[1]);
                    mma_bf(s[grp][4*ph+1], ah[grp], b0l[2], b0l[3]);
                    mma_bf(s[grp][4*ph+2], ah[grp], b1l[0], b1l[1]);
                    mma_bf(s[grp][4*ph+3], ah[grp], b1l[2], b1l[3]);
                    mma_bf(s[grp][4*ph+0], al[grp], b0h[0], b0h[1]);
                    mma_bf(s[grp][4*ph+1], al[grp], b0h[2], b0h[3]);
                    mma_bf(s[grp][4*ph+2], al[grp], b1h[0], b1h[1]);
                    mma_bf(s[grp][4*ph+3], al[grp], b1h[2], b1h[3]);
                }
            }
        }

        // ---- online softmax (4 rows/thread: grp x {g, g+8}) ----
        #pragma unroll
        for (int grp = 0; grp < 2; grp++){
            #pragma unroll
            for (int ri = 0; ri < 2; ri++){
                float mi = -3e38f;
                #pragma unroll
                for (int nb = 0; nb < 8; nb++)
                    mi = fmaxf(mi, fmaxf(s[grp][nb][2*ri], s[grp][nb][2*ri+1]));
                mi = fmaxf(mi, __shfl_xor_sync(0xffffffffu, mi, 1));
                mi = fmaxf(mi, __shfl_xor_sync(0xffffffffu, mi, 2));
                float mnew = fmaxf(mr[grp][ri], mi);
                float sc = __expf(mr[grp][ri] - mnew);
                mr[grp][ri] = mnew;
                float li = 0.f;
                #pragma unroll
                for (int nb = 0; nb < 8; nb++){
                    float e0 = __expf(s[grp][nb][2*ri]   - mnew);
                    float e1 = __expf(s[grp][nb][2*ri+1] - mnew);
                    s[grp][nb][2*ri] = e0; s[grp][nb][2*ri+1] = e1;
                    li += e0 + e1;
                    o[grp][nb][2*ri]   *= sc;
                    o[grp][nb][2*ri+1] *= sc;
                }
                li += __shfl_xor_sync(0xffffffffu, li, 1);
                li += __shfl_xor_sync(0xffffffffu, li, 2);
                lr[grp][ri] = lr[grp][ri]*sc + li;
            }
        }

        // ---- P convert (hi only) + O += P @ V (2 products) ----
        #pragma unroll
        for (int ks = 0; ks < 4; ks++){
            u32 ph4[2][4];
            #pragma unroll
            for (int grp = 0; grp < 2; grp++){
                ph4[grp][0] = packbf(s[grp][2*ks][0],   s[grp][2*ks][1]);
                ph4[grp][1] = packbf(s[grp][2*ks][2],   s[grp][2*ks][3]);
                ph4[grp][2] = packbf(s[grp][2*ks+1][0], s[grp][2*ks+1][1]);
                ph4[grp][3] = packbf(s[grp][2*ks+1][2], s[grp][2*ks+1][3]);
            }
            #pragma unroll
            for (int ph = 0; ph < 2; ph++){
                u32 v0h[4], v1h[4], v0l[4], v1l[4];
                ldsm4(v0h[0],v0h[1],v0h[2],v0h[3], vh_b + (2*ph)*2304   + ks*32);
                ldsm4(v1h[0],v1h[1],v1h[2],v1h[3], vh_b + (2*ph+1)*2304 + ks*32);
                ldsm4(v0l[0],v0l[1],v0l[2],v0l[3], vl_b + (2*ph)*2304   + ks*32);
                ldsm4(v1l[0],v1l[1],v1l[2],v1l[3], vl_b + (2*ph+1)*2304 + ks*32);
                #pragma unroll
                for (int grp = 0; grp < 2; grp++){
                    mma_bf(o[grp][4*ph+0], ph4[grp], v0h[0], v0h[1]);
                    mma_bf(o[grp][4*ph+1], ph4[grp], v0h[2], v0h[3]);
                    mma_bf(o[grp][4*ph+2], ph4[grp], v1h[0], v1h[1]);
                    mma_bf(o[grp][4*ph+3], ph4[grp], v1h[2], v1h[3]);
                    mma_bf(o[grp][4*ph+0], ph4[grp], v0l[0], v0l[1]);
                    mma_bf(o[grp][4*ph+1], ph4[grp], v0l[2], v0l[3]);
                    mma_bf(o[grp][4*ph+2], ph4[grp], v1l[0], v1l[1]);
                    mma_bf(o[grp][4*ph+3], ph4[grp], v1l[2], v1l[3]);
                }
            }
        }

        __syncthreads();            // all warps done with buffer it&1
        if (it + 2 < KT_PER){ stage(it + 2, it & 1); }
        CP_COMMIT();                // keep group accounting uniform
    }

    // ---- write unnormalized partials + stats ----
    const int g = lane >> 2, t2 = lane & 3;
    #pragma unroll
    for (int grp = 0; grp < 2; grp++){
        const int r0 = base + q0 + 32*wid + 16*grp + g, r1 = r0 + 8;
        #pragma unroll
        for (int nb = 0; nb < 8; nb++){
            *(float2*)&g_Op[z][(size_t)r0*DH + nb*8 + t2*2] = make_float2(o[grp][nb][0], o[grp][nb][1]);
            *(float2*)&g_Op[z][(size_t)r1*DH + nb*8 + t2*2] = make_float2(o[grp][nb][2], o[grp][nb][3]);
        }
        if (t2 == 0){
            g_m[z][r0] = mr[grp][0]; g_l[z][r0] = lr[grp][0];
            g_m[z][r1] = mr[grp][1]; g_l[z][r1] = lr[grp][1];
        }
    }
}

// ---------------- kernel: flash split combine + mask -----------------------
__global__ __launch_bounds__(256) void combine(const float* __restrict__ mask,
                                               float* __restrict__ out){
    int idx = blockIdx.x*256 + threadIdx.x;   // row*16 + dquad
    int row = idx >> 4, dq = idx & 15;
    float mm = -3e38f;
    #pragma unroll
    for (int z = 0; z < NSPLIT; z++) mm = fmaxf(mm, g_m[z][row]);
    float den = 0.f;
    float4 r = make_float4(0.f, 0.f, 0.f, 0.f);
    #pragma unroll
    for (int z = 0; z < NSPLIT; z++){
        float wz = __expf(g_m[z][row] - mm);
        den += wz * g_l[z][row];
        float4 a = *(const float4*)&g_Op[z][(size_t)row*DH + dq*4];
        r.x += a.x*wz; r.y += a.y*wz; r.z += a.z*wz; r.w += a.w*wz;
    }
    float f = mask[row] / den;
    r.x *= f; r.y *= f; r.z *= f; r.w *= f;
    *(float4*)&out[(size_t)row*DH + dq*4] = r;
}

// ---------------------------------------------------------------------------
extern "C" void kernel_launch(void* const* d_in, const int* in_sizes, int n_in,
                              void* d_out, int out_size)
{
    const float* X    = (const float*)d_in[0];
    const float* mask = (const float*)d_in[1];
    const float* Wq   = (const float*)d_in[2];
    const float* bq   = (const float*)d_in[3];
    const float* Wk   = (const float*)d_in[4];
    const float* bk   = (const float*)d_in[5];
    const float* Wv   = (const float*)d_in[6];
    const float* bv   = (const float*)d_in[7];

    // attn smem: Qh+Ql (128x72) + 2 x [Kh,Kl,Vh,Vl] (64x72 each) -> 110592 B
    const int smem_attn = (2*128*72 + 2*4*64*72) * (int)sizeof(u16);
    cudaFuncSetAttribute(attn_mma,
                         cudaFuncAttributeMaxDynamicSharedMemorySize, smem_attn);
    // qkv smem: Xh+Xl (128x72) + Wh,Wl (64x72) -> 55296 B
    const int smem_qkv = (2*128*72 + 2*64*72) * (int)sizeof(u16);
    cudaFuncSetAttribute(qkv_mma,
                         cudaFuncAttributeMaxDynamicSharedMemorySize, smem_qkv);

    cvt_w<<<3*DH*DIN/256, 256>>>(Wq, Wk, Wv);
    qkv_mma<<<dim3(MROWS/128, 3), 128, smem_qkv>>>(X, bq, bk, bv);
    attn_mma<<<dim3(SS/128, BB, NSPLIT), 128, smem_attn>>>();
    combine<<<MROWS*DH/4/256, 256>>>(mask, (float*)d_out);
}

// round 14
// speedup vs baseline: 1.0826x; 1.0826x over previous
#include <cuda_runtime.h>

typedef unsigned int u32;
typedef unsigned short u16;

#define BB 4
#define SS 4096
#define DIN 1024
#define DH 64
#define MROWS (BB*SS)
#define NSPLIT 8
#define KTS (SS/64)
#define KT_PER (KTS/NSPLIT)
#define LOG2E 1.4426950408889634f

// ---------------- scratch (static device memory; no allocations) ----------
__device__ u16 g_Wth[3][DH*DIN], g_Wtl[3][DH*DIN];         // W^T split bf16 [out][din]
__device__ u16 g_Qh[MROWS*DH], g_Ql[MROWS*DH];             // [row][d], pre-scaled by log2e
__device__ u16 g_Kh[MROWS*DH], g_Kl[MROWS*DH];             // [row][d]
__device__ u16 g_Vh[MROWS*DH], g_Vl[MROWS*DH];             // transposed [b][d][s]
__device__ float g_Op[NSPLIT][MROWS*DH];                   // unnormalized partial O
__device__ float g_m[NSPLIT][MROWS];                       // running max (log2 domain)
__device__ float g_l[NSPLIT][MROWS];

// ---------------- helpers --------------------------------------------------
__device__ __forceinline__ u32 packbf(float lo, float hi){
    u32 r; asm("cvt.rn.bf16x2.f32 %0, %1, %2;" : "=r"(r) : "f"(hi), "f"(lo)); return r;
}
__device__ __forceinline__ float bflo(u32 p){ return __uint_as_float(p << 16); }
__device__ __forceinline__ float bfhi(u32 p){ return __uint_as_float(p & 0xffff0000u); }
__device__ __forceinline__ u32 smaddr(const void* p){ return (u32)__cvta_generic_to_shared(p); }
__device__ __forceinline__ float ex2f(float x){
    float r; asm("ex2.approx.f32 %0, %1;" : "=f"(r) : "f"(x)); return r;
}

__device__ __forceinline__ void ldsm4(u32& r0,u32& r1,u32& r2,u32& r3, u32 a){
    asm volatile("ldmatrix.sync.aligned.m8n8.x4.shared.b16 {%0,%1,%2,%3}, [%4];"
        : "=r"(r0),"=r"(r1),"=r"(r2),"=r"(r3) : "r"(a));
}
__device__ __forceinline__ void mma_bf(float* c, const u32* a, u32 b0, u32 b1){
    asm volatile("mma.sync.aligned.m16n8k16.row.col.f32.bf16.bf16.f32 "
        "{%0,%1,%2,%3},{%4,%5,%6,%7},{%8,%9},{%0,%1,%2,%3};"
        : "+f"(c[0]),"+f"(c[1]),"+f"(c[2]),"+f"(c[3])
        : "r"(a[0]),"r"(a[1]),"r"(a[2]),"r"(a[3]),"r"(b0),"r"(b1));
}

// ---------------- kernel: convert+transpose weights ------------------------
__global__ __launch_bounds__(256) void cvt_w(const float* __restrict__ Wq,
                                             const float* __restrict__ Wk,
                                             const float* __restrict__ Wv){
    int id = blockIdx.x*256 + threadIdx.x;
    int w = id >> 16; int r = id & 65535;
    int n = r >> 10, k = r & 1023;
    const float* W = (w==0) ? Wq : (w==1) ? Wk : Wv;
    float x = W[k*DH + n];
    u32 p = packbf(x, 0.f);
    u32 q = packbf(x - bflo(p), 0.f);
    g_Wth[w][n*DIN + k] = (u16)(p & 0xffff);
    g_Wtl[w][n*DIN + k] = (u16)(q & 0xffff);
}

__device__ __forceinline__ void storeV(int r, int c, float v){
    int bb = r >> 12, s = r & 4095;
    u32 p = packbf(v, 0.f);
    g_Vh[(size_t)(bb*64 + c)*SS + s] = (u16)(p & 0xffff);
    u32 q = packbf(v - bflo(p), 0.f);
    g_Vl[(size_t)(bb*64 + c)*SS + s] = (u16)(q & 0xffff);
}

// ---------------- kernel: QKV projection via HMMA, fused X split -----------
// grid (MROWS/128, 3), 128 threads. 4 warps x 2 x m16 groups = 128 rows/CTA.
// Q output is pre-scaled by log2e so attention S is in log2 domain.
__global__ __launch_bounds__(128, 3) void qkv_mma(
    const float* __restrict__ X,
    const float* __restrict__ bq, const float* __restrict__ bk,
    const float* __restrict__ bv)
{
    extern __shared__ u16 smq[];
    u16* Xs_h = smq;               // 128*72
    u16* Xs_l = Xs_h + 128*72;
    u16* Ws_h = Xs_l + 128*72;     // 64*72
    u16* Ws_l = Ws_h + 64*72;

    const int t = threadIdx.x, lane = t & 31, warp = t >> 5;
    const int w = blockIdx.y;
    const int m0 = blockIdx.x * 128;
    const u16* Wth = g_Wth[w]; const u16* Wtl = g_Wtl[w];
    const float* bias = (w==0) ? bq : (w==1) ? bk : bv;
    const float oscale = (w==0) ? LOG2E : 1.0f;

    u32 a_h[2], a_l[2];
    #pragma unroll
    for (int grp = 0; grp < 2; grp++){
        u32 aoff = ((u32)(32*warp + 16*grp + (lane&15))*72 + ((lane>>4)<<3)) * 2;
        a_h[grp] = smaddr(Xs_h) + aoff;
        a_l[grp] = smaddr(Xs_l) + aoff;
    }
    const u32 boff = (((lane&7) + ((lane>>4)<<3))*72 + (((lane>>3)&1)<<3)) * 2;
    const u32 b_h = smaddr(Ws_h) + boff, b_l = smaddr(Ws_l) + boff;

    float acc[2][8][4] = {};
    for (int c16 = 0; c16 < 16; c16++){
        __syncthreads();
        #pragma unroll
        for (int u = 0; u < 8; u++){
            int idx = t + 128*u; int row = idx >> 3, q4 = idx & 7;
            const float* xp = &X[(size_t)(m0+row)*DIN + c16*64 + q4*8];
            float4 v0 = *(const float4*)xp;
            float4 v1 = *(const float4*)(xp + 4);
            u32 h01 = packbf(v0.x, v0.y), h23 = packbf(v0.z, v0.w);
            u32 h45 = packbf(v1.x, v1.y), h67 = packbf(v1.z, v1.w);
            u32 l01 = packbf(v0.x - bflo(h01), v0.y - bfhi(h01));
            u32 l23 = packbf(v0.z - bflo(h23), v0.w - bfhi(h23));
            u32 l45 = packbf(v1.x - bflo(h45), v1.y - bfhi(h45));
            u32 l67 = packbf(v1.z - bflo(h67), v1.w - bfhi(h67));
            *(uint4*)&Xs_h[row*72 + q4*8] = make_uint4(h01, h23, h45, h67);
            *(uint4*)&Xs_l[row*72 + q4*8] = make_uint4(l01, l23, l45, l67);
        }
        #pragma unroll
        for (int u = 0; u < 4; u++){
            int idx = t + 128*u; int row = idx >> 3, q4 = idx & 7;
            *(uint4*)&Ws_h[row*72 + q4*8] = *(const uint4*)&Wth[(size_t)row*DIN + c16*64 + q4*8];
            *(uint4*)&Ws_l[row*72 + q4*8] = *(const uint4*)&Wtl[(size_t)row*DIN + c16*64 + q4*8];
        }
        __syncthreads();
        #pragma unroll
        for (int ks = 0; ks < 4; ks++){
            u32 ah[2][4], al[2][4];
            #pragma unroll
            for (int grp = 0; grp < 2; grp++){
                ldsm4(ah[grp][0],ah[grp][1],ah[grp][2],ah[grp][3], a_h[grp] + ks*32);
                ldsm4(al[grp][0],al[grp][1],al[grp][2],al[grp][3], a_l[grp] + ks*32);
            }
            #pragma unroll
            for (int ph = 0; ph < 2; ph++){
                u32 b0h[4], b1h[4], b0l[4], b1l[4];
                ldsm4(b0h[0],b0h[1],b0h[2],b0h[3], b_h + (2*ph)*2304   + ks*32);
                ldsm4(b1h[0],b1h[1],b1h[2],b1h[3], b_h + (2*ph+1)*2304 + ks*32);
                ldsm4(b0l[0],b0l[1],b0l[2],b0l[3], b_l + (2*ph)*2304   + ks*32);
                ldsm4(b1l[0],b1l[1],b1l[2],b1l[3], b_l + (2*ph+1)*2304 + ks*32);
                #pragma unroll
                for (int grp = 0; grp < 2; grp++){
                    mma_bf(acc[grp][4*ph+0], ah[grp], b0h[0], b0h[1]);
                    mma_bf(acc[grp][4*ph+1], ah[grp], b0h[2], b0h[3]);
                    mma_bf(acc[grp][4*ph+2], ah[grp], b1h[0], b1h[1]);
                    mma_bf(acc[grp][4*ph+3], ah[grp], b1h[2], b1h[3]);
                    mma_bf(acc[grp][4*ph+0], ah[grp], b0l[0], b0l[1]);
                    mma_bf(acc[grp][4*ph+1], ah[grp], b0l[2], b0l[3]);
                    mma_bf(acc[grp][4*ph+2], ah[grp], b1l[0], b1l[1]);
                    mma_bf(acc[grp][4*ph+3], ah[grp], b1l[2], b1l[3]);
                    mma_bf(acc[grp][4*ph+0], al[grp], b0h[0], b0h[1]);
                    mma_bf(acc[grp][4*ph+1], al[grp], b0h[2], b0h[3]);
                    mma_bf(acc[grp][4*ph+2], al[grp], b1h[0], b1h[1]);
                    mma_bf(acc[grp][4*ph+3], al[grp], b1h[2], b1h[3]);
                }
            }
        }
    }

    const int g = lane >> 2, t2 = lane & 3;
    #pragma unroll
    for (int grp = 0; grp < 2; grp++){
        const int r0 = m0 + 32*warp + 16*grp + g, r1 = r0 + 8;
        #pragma unroll
        for (int nb = 0; nb < 8; nb++){
            int col = nb*8 + t2*2;
            float b0v = bias[col], b1v = bias[col+1];
            float v00 = fmaxf(acc[grp][nb][0] + b0v, 0.f) * oscale;
            float v01 = fmaxf(acc[grp][nb][1] + b1v, 0.f) * oscale;
            float v10 = fmaxf(acc[grp][nb][2] + b0v, 0.f) * oscale;
            float v11 = fmaxf(acc[grp][nb][3] + b1v, 0.f) * oscale;
            if (w == 2){
                storeV(r0, col, v00); storeV(r0, col+1, v01);
                storeV(r1, col, v10); storeV(r1, col+1, v11);
            } else {
                u16* Oh = (w==0) ? g_Qh : g_Kh;
                u16* Ol = (w==0) ? g_Ql : g_Kl;
                u32 h = packbf(v00, v01);
                u32 lo = packbf(v00 - bflo(h), v01 - bfhi(h));
                *(u32*)&Oh[(size_t)r0*DH + col] = h; *(u32*)&Ol[(size_t)r0*DH + col] = lo;
                h = packbf(v10, v11);
                lo = packbf(v10 - bflo(h), v11 - bfhi(h));
                *(u32*)&Oh[(size_t)r1*DH + col] = h; *(u32*)&Ol[(size_t)r1*DH + col] = lo;
            }
        }
    }
}

// ---------------- kernel: flash attention via HMMA (R12 structure) ---------
// grid (SS/128, BB, NSPLIT), 128 threads. Bq=128 (4 warps x 32 rows), Bk=64.
// S in log2 domain (Q pre-scaled); exp via bare ex2.approx.
// PV uses 2 split-products (P_hi*V_hi + P_hi*V_lo).
__global__ __launch_bounds__(128, 2) void attn_mma()
{
    extern __shared__ u16 smu[];
    u16* Qh = smu;                 // 128*72
    u16* Ql = Qh + 128*72;
    u16* Kh = Ql + 128*72;         // 64*72 each below
    u16* Kl = Kh + 64*72;
    u16* Vh = Kl + 64*72;
    u16* Vl = Vh + 64*72;

    const int t = threadIdx.x, lane = t & 31, wid = t >> 5;
    const int b = blockIdx.y, z = blockIdx.z;
    const int q0 = blockIdx.x * 128;
    const int base = b * SS;

    // stage Q (128 rows, hi+lo)
    #pragma unroll
    for (int u = 0; u < 8; u++){
        int idx = t + 128*u; int row = idx >> 3, q4 = idx & 7;
        *(uint4*)&Qh[row*72 + q4*8] = *(const uint4*)&g_Qh[(size_t)(base+q0+row)*DH + q4*8];
        *(uint4*)&Ql[row*72 + q4*8] = *(const uint4*)&g_Ql[(size_t)(base+q0+row)*DH + q4*8];
    }

    u32 qh_a[2], ql_a[2];
    #pragma unroll
    for (int grp = 0; grp < 2; grp++){
        u32 aoff = ((u32)(32*wid + 16*grp + (lane&15))*72 + ((lane>>4)<<3)) * 2;
        qh_a[grp] = smaddr(Qh) + aoff;
        ql_a[grp] = smaddr(Ql) + aoff;
    }
    const u32 boff = (((lane&7) + ((lane>>4)<<3))*72 + (((lane>>3)&1)<<3)) * 2;
    const u32 kh_b = smaddr(Kh) + boff, kl_b = smaddr(Kl) + boff;
    const u32 vh_b = smaddr(Vh) + boff, vl_b = smaddr(Vl) + boff;

    float o[2][8][4] = {};
    float mr[2][2] = {{-3e38f,-3e38f},{-3e38f,-3e38f}};
    float lr[2][2] = {{0.f,0.f},{0.f,0.f}};

    for (int it = 0; it < KT_PER; it++){
        const int k0 = (z*KT_PER + it) * 64;
        __syncthreads();
        #pragma unroll
        for (int u = 0; u < 4; u++){
            int idx = t + 128*u; int row = idx >> 3, q4 = idx & 7;
            *(uint4*)&Kh[row*72 + q4*8] = *(const uint4*)&g_Kh[(size_t)(base+k0+row)*DH + q4*8];
            *(uint4*)&Kl[row*72 + q4*8] = *(const uint4*)&g_Kl[(size_t)(base+k0+row)*DH + q4*8];
            *(uint4*)&Vh[row*72 + q4*8] = *(const uint4*)&g_Vh[(size_t)(b*64+row)*SS + k0 + q4*8];
            *(uint4*)&Vl[row*72 + q4*8] = *(const uint4*)&g_Vl[(size_t)(b*64+row)*SS + k0 + q4*8];
        }
        __syncthreads();

        // ---- S = Q @ K^T (full 3-product split) ----
        float s[2][8][4] = {};
        #pragma unroll
        for (int ks = 0; ks < 4; ks++){
            u32 ah[2][4], al[2][4];
            #pragma unroll
            for (int grp = 0; grp < 2; grp++){
                ldsm4(ah[grp][0],ah[grp][1],ah[grp][2],ah[grp][3], qh_a[grp] + ks*32);
                ldsm4(al[grp][0],al[grp][1],al[grp][2],al[grp][3], ql_a[grp] + ks*32);
            }
            #pragma unroll
            for (int ph = 0; ph < 2; ph++){
                u32 b0h[4], b1h[4], b0l[4], b1l[4];
                ldsm4(b0h[0],b0h[1],b0h[2],b0h[3], kh_b + (2*ph)*2304   + ks*32);
                ldsm4(b1h[0],b1h[1],b1h[2],b1h[3], kh_b + (2*ph+1)*2304 + ks*32);
                ldsm4(b0l[0],b0l[1],b0l[2],b0l[3], kl_b + (2*ph)*2304   + ks*32);
                ldsm4(b1l[0],b1l[1],b1l[2],b1l[3], kl_b + (2*ph+1)*2304 + ks*32);
                #pragma unroll
                for (int grp = 0; grp < 2; grp++){
                    mma_bf(s[grp][4*ph+0], ah[grp], b0h[0], b0h[1]);
                    mma_bf(s[grp][4*ph+1], ah[grp], b0h[2], b0h[3]);
                    mma_bf(s[grp][4*ph+2], ah[grp], b1h[0], b1h[1]);
                    mma_bf(s[grp][4*ph+3], ah[grp], b1h[2], b1h[3]);
                    mma_bf(s[grp][4*ph+0], ah[grp], b0l[0], b0l[1]);
                    mma_bf(s[grp][4*ph+1], ah[grp], b0l[2], b0l[3]);
                    mma_bf(s[grp][4*ph+2], ah[grp], b1l[0], b1l[1]);
                    mma_bf(s[grp][4*ph+3], ah[grp], b1l[2], b1l[3]);
                    mma_bf(s[grp][4*ph+0], al[grp], b0h[0], b0h[1]);
                    mma_bf(s[grp][4*ph+1], al[grp], b0h[2], b0h[3]);
                    mma_bf(s[grp][4*ph+2], al[grp], b1h[0], b1h[1]);
                    mma_bf(s[grp][4*ph+3], al[grp], b1h[2], b1h[3]);
                }
            }
        }

        // ---- online softmax in log2 domain (4 rows/thread) ----
        #pragma unroll
        for (int grp = 0; grp < 2; grp++){
            #pragma unroll
            for (int ri = 0; ri < 2; ri++){
                float mi = -3e38f;
                #pragma unroll
                for (int nb = 0; nb < 8; nb++)
                    mi = fmaxf(mi, fmaxf(s[grp][nb][2*ri], s[grp][nb][2*ri+1]));
                mi = fmaxf(mi, __shfl_xor_sync(0xffffffffu, mi, 1));
                mi = fmaxf(mi, __shfl_xor_sync(0xffffffffu, mi, 2));
                float mnew = fmaxf(mr[grp][ri], mi);
                float sc = ex2f(mr[grp][ri] - mnew);
                mr[grp][ri] = mnew;
                float li = 0.f;
                #pragma unroll
                for (int nb = 0; nb < 8; nb++){
                    float e0 = ex2f(s[grp][nb][2*ri]   - mnew);
                    float e1 = ex2f(s[grp][nb][2*ri+1] - mnew);
                    s[grp][nb][2*ri] = e0; s[grp][nb][2*ri+1] = e1;
                    li += e0 + e1;
                    o[grp][nb][2*ri]   *= sc;
                    o[grp][nb][2*ri+1] *= sc;
                }
                li += __shfl_xor_sync(0xffffffffu, li, 1);
                li += __shfl_xor_sync(0xffffffffu, li, 2);
                lr[grp][ri] = lr[grp][ri]*sc + li;
            }
        }

        // ---- P convert (hi only) + O += P @ V (2 products) ----
        #pragma unroll
        for (int ks = 0; ks < 4; ks++){
            u32 ph4[2][4];
            #pragma unroll
            for (int grp = 0; grp < 2; grp++){
                ph4[grp][0] = packbf(s[grp][2*ks][0],   s[grp][2*ks][1]);
                ph4[grp][1] = packbf(s[grp][2*ks][2],   s[grp][2*ks][3]);
                ph4[grp][2] = packbf(s[grp][2*ks+1][0], s[grp][2*ks+1][1]);
                ph4[grp][3] = packbf(s[grp][2*ks+1][2], s[grp][2*ks+1][3]);
            }
            #pragma unroll
            for (int ph = 0; ph < 2; ph++){
                u32 v0h[4], v1h[4], v0l[4], v1l[4];
                ldsm4(v0h[0],v0h[1],v0h[2],v0h[3], vh_b + (2*ph)*2304   + ks*32);
                ldsm4(v1h[0],v1h[1],v1h[2],v1h[3], vh_b + (2*ph+1)*2304 + ks*32);
                ldsm4(v0l[0],v0l[1],v0l[2],v0l[3], vl_b + (2*ph)*2304   + ks*32);
                ldsm4(v1l[0],v1l[1],v1l[2],v1l[3], vl_b + (2*ph+1)*2304 + ks*32);
                #pragma unroll
                for (int grp = 0; grp < 2; grp++){
                    mma_bf(o[grp][4*ph+0], ph4[grp], v0h[0], v0h[1]);
                    mma_bf(o[grp][4*ph+1], ph4[grp], v0h[2], v0h[3]);
                    mma_bf(o[grp][4*ph+2], ph4[grp], v1h[0], v1h[1]);
                    mma_bf(o[grp][4*ph+3], ph4[grp], v1h[2], v1h[3]);
                    mma_bf(o[grp][4*ph+0], ph4[grp], v0l[0], v0l[1]);
                    mma_bf(o[grp][4*ph+1], ph4[grp], v0l[2], v0l[3]);
                    mma_bf(o[grp][4*ph+2], ph4[grp], v1l[0], v1l[1]);
                    mma_bf(o[grp][4*ph+3], ph4[grp], v1l[2], v1l[3]);
                }
            }
        }
    }

    // ---- write unnormalized partials + stats ----
    const int g = lane >> 2, t2 = lane & 3;
    #pragma unroll
    for (int grp = 0; grp < 2; grp++){
        const int r0 = base + q0 + 32*wid + 16*grp + g, r1 = r0 + 8;
        #pragma unroll
        for (int nb = 0; nb < 8; nb++){
            *(float2*)&g_Op[z][(size_t)r0*DH + nb*8 + t2*2] = make_float2(o[grp][nb][0], o[grp][nb][1]);
            *(float2*)&g_Op[z][(size_t)r1*DH + nb*8 + t2*2] = make_float2(o[grp][nb][2], o[grp][nb][3]);
        }
        if (t2 == 0){
            g_m[z][r0] = mr[grp][0]; g_l[z][r0] = lr[grp][0];
            g_m[z][r1] = mr[grp][1]; g_l[z][r1] = lr[grp][1];
        }
    }
}

// ---------------- kernel: flash split combine + mask (log2 domain) ---------
__global__ __launch_bounds__(256) void combine(const float* __restrict__ mask,
                                               float* __restrict__ out){
    int idx = blockIdx.x*256 + threadIdx.x;   // row*16 + dquad
    int row = idx >> 4, dq = idx & 15;
    float mm = -3e38f;
    #pragma unroll
    for (int z = 0; z < NSPLIT; z++) mm = fmaxf(mm, g_m[z][row]);
    float den = 0.f;
    float4 r = make_float4(0.f, 0.f, 0.f, 0.f);
    #pragma unroll
    for (int z = 0; z < NSPLIT; z++){
        float wz = ex2f(g_m[z][row] - mm);
        den += wz * g_l[z][row];
        float4 a = *(const float4*)&g_Op[z][(size_t)row*DH + dq*4];
        r.x += a.x*wz; r.y += a.y*wz; r.z += a.z*wz; r.w += a.w*wz;
    }
    float f = mask[row] / den;
    r.x *= f; r.y *= f; r.z *= f; r.w *= f;
    *(float4*)&out[(size_t)row*DH + dq*4] = r;
}

// ---------------------------------------------------------------------------
extern "C" void kernel_launch(void* const* d_in, const int* in_sizes, int n_in,
                              void* d_out, int out_size)
{
    const float* X    = (const float*)d_in[0];
    const float* mask = (const float*)d_in[1];
    const float* Wq   = (const float*)d_in[2];
    const float* bq   = (const float*)d_in[3];
    const float* Wk   = (const float*)d_in[4];
    const float* bk   = (const float*)d_in[5];
    const float* Wv   = (const float*)d_in[6];
    const float* bv   = (const float*)d_in[7];

    // attn smem: Qh+Ql (128x72) + Kh,Kl,Vh,Vl (64x72), u16 -> 73728 B
    const int smem_attn = (2*128*72 + 4*64*72) * (int)sizeof(u16);
    cudaFuncSetAttribute(attn_mma,
                         cudaFuncAttributeMaxDynamicSharedMemorySize, smem_attn);
    // qkv smem: Xh+Xl (128x72) + Wh,Wl (64x72), u16 -> 55296 B
    const int smem_qkv = (2*128*72 + 2*64*72) * (int)sizeof(u16);
    cudaFuncSetAttribute(qkv_mma,
                         cudaFuncAttributeMaxDynamicSharedMemorySize, smem_qkv);

    cvt_w<<<3*DH*DIN/256, 256>>>(Wq, Wk, Wv);
    qkv_mma<<<dim3(MROWS/128, 3), 128, smem_qkv>>>(X, bq, bk, bv);
    attn_mma<<<dim3(SS/128, BB, NSPLIT), 128, smem_attn>>>();
    combine<<<MROWS*DH/4/256, 256>>>(mask, (float*)d_out);
}

// round 15
// speedup vs baseline: 1.1272x; 1.0413x over previous
#include <cuda_runtime.h>

typedef unsigned int u32;
typedef unsigned short u16;

#define BB 4
#define SS 4096
#define DIN 1024
#define DH 64
#define MROWS (BB*SS)
#define NSPLIT 8
#define KTS (SS/64)
#define KT_PER (KTS/NSPLIT)
#define LOG2E 1.4426950408889634f

// ---------------- scratch (static device memory; no allocations) ----------
__device__ u16 g_Wth[3][DH*DIN], g_Wtl[3][DH*DIN];         // W^T split bf16 [out][din]
__device__ u16 g_Qh[MROWS*DH], g_Ql[MROWS*DH];             // [row][d], pre-scaled by log2e
__device__ u16 g_Kh[MROWS*DH], g_Kl[MROWS*DH];             // [row][d]
__device__ u16 g_Vh[MROWS*DH];                             // transposed [b][d][s], hi only
__device__ float g_Op[NSPLIT][MROWS*DH];                   // unnormalized partial O
__device__ float g_m[NSPLIT][MROWS];                       // running max (log2 domain)
__device__ float g_l[NSPLIT][MROWS];

// ---------------- helpers --------------------------------------------------
__device__ __forceinline__ u32 packbf(float lo, float hi){
    u32 r; asm("cvt.rn.bf16x2.f32 %0, %1, %2;" : "=r"(r) : "f"(hi), "f"(lo)); return r;
}
__device__ __forceinline__ float bflo(u32 p){ return __uint_as_float(p << 16); }
__device__ __forceinline__ float bfhi(u32 p){ return __uint_as_float(p & 0xffff0000u); }
__device__ __forceinline__ u32 smaddr(const void* p){ return (u32)__cvta_generic_to_shared(p); }
__device__ __forceinline__ float ex2f(float x){
    float r; asm("ex2.approx.f32 %0, %1;" : "=f"(r) : "f"(x)); return r;
}

__device__ __forceinline__ void ldsm4(u32& r0,u32& r1,u32& r2,u32& r3, u32 a){
    asm volatile("ldmatrix.sync.aligned.m8n8.x4.shared.b16 {%0,%1,%2,%3}, [%4];"
        : "=r"(r0),"=r"(r1),"=r"(r2),"=r"(r3) : "r"(a));
}
__device__ __forceinline__ void mma_bf(float* c, const u32* a, u32 b0, u32 b1){
    asm volatile("mma.sync.aligned.m16n8k16.row.col.f32.bf16.bf16.f32 "
        "{%0,%1,%2,%3},{%4,%5,%6,%7},{%8,%9},{%0,%1,%2,%3};"
        : "+f"(c[0]),"+f"(c[1]),"+f"(c[2]),"+f"(c[3])
        : "r"(a[0]),"r"(a[1]),"r"(a[2]),"r"(a[3]),"r"(b0),"r"(b1));
}

// ---------------- kernel: convert+transpose weights ------------------------
__global__ __launch_bounds__(256) void cvt_w(const float* __restrict__ Wq,
                                             const float* __restrict__ Wk,
                                             const float* __restrict__ Wv){
    int id = blockIdx.x*256 + threadIdx.x;
    int w = id >> 16; int r = id & 65535;
    int n = r >> 10, k = r & 1023;
    const float* W = (w==0) ? Wq : (w==1) ? Wk : Wv;
    float x = W[k*DH + n];
    u32 p = packbf(x, 0.f);
    u32 q = packbf(x - bflo(p), 0.f);
    g_Wth[w][n*DIN + k] = (u16)(p & 0xffff);
    g_Wtl[w][n*DIN + k] = (u16)(q & 0xffff);
}

__device__ __forceinline__ void storeV(int r, int c, float v){
    int bb = r >> 12, s = r & 4095;
    u32 p = packbf(v, 0.f);
    g_Vh[(size_t)(bb*64 + c)*SS + s] = (u16)(p & 0xffff);
}

// ---------------- kernel: QKV projection via HMMA, fused X split -----------
// grid (MROWS/128, 3), 128 threads. 4 warps x 2 x m16 groups = 128 rows/CTA.
// Q output is pre-scaled by log2e so attention S is in log2 domain.
__global__ __launch_bounds__(128, 3) void qkv_mma(
    const float* __restrict__ X,
    const float* __restrict__ bq, const float* __restrict__ bk,
    const float* __restrict__ bv)
{
    extern __shared__ u16 smq[];
    u16* Xs_h = smq;               // 128*72
    u16* Xs_l = Xs_h + 128*72;
    u16* Ws_h = Xs_l + 128*72;     // 64*72
    u16* Ws_l = Ws_h + 64*72;

    const int t = threadIdx.x, lane = t & 31, warp = t >> 5;
    const int w = blockIdx.y;
    const int m0 = blockIdx.x * 128;
    const u16* Wth = g_Wth[w]; const u16* Wtl = g_Wtl[w];
    const float* bias = (w==0) ? bq : (w==1) ? bk : bv;
    const float oscale = (w==0) ? LOG2E : 1.0f;

    u32 a_h[2], a_l[2];
    #pragma unroll
    for (int grp = 0; grp < 2; grp++){
        u32 aoff = ((u32)(32*warp + 16*grp + (lane&15))*72 + ((lane>>4)<<3)) * 2;
        a_h[grp] = smaddr(Xs_h) + aoff;
        a_l[grp] = smaddr(Xs_l) + aoff;
    }
    const u32 boff = (((lane&7) + ((lane>>4)<<3))*72 + (((lane>>3)&1)<<3)) * 2;
    const u32 b_h = smaddr(Ws_h) + boff, b_l = smaddr(Ws_l) + boff;

    float acc[2][8][4] = {};
    for (int c16 = 0; c16 < 16; c16++){
        __syncthreads();
        #pragma unroll
        for (int u = 0; u < 8; u++){
            int idx = t + 128*u; int row = idx >> 3, q4 = idx & 7;
            const float* xp = &X[(size_t)(m0+row)*DIN + c16*64 + q4*8];
            float4 v0 = *(const float4*)xp;
            float4 v1 = *(const float4*)(xp + 4);
            u32 h01 = packbf(v0.x, v0.y), h23 = packbf(v0.z, v0.w);
            u32 h45 = packbf(v1.x, v1.y), h67 = packbf(v1.z, v1.w);
            u32 l01 = packbf(v0.x - bflo(h01), v0.y - bfhi(h01));
            u32 l23 = packbf(v0.z - bflo(h23), v0.w - bfhi(h23));
            u32 l45 = packbf(v1.x - bflo(h45), v1.y - bfhi(h45));
            u32 l67 = packbf(v1.z - bflo(h67), v1.w - bfhi(h67));
            *(uint4*)&Xs_h[row*72 + q4*8] = make_uint4(h01, h23, h45, h67);
            *(uint4*)&Xs_l[row*72 + q4*8] = make_uint4(l01, l23, l45, l67);
        }
        #pragma unroll
        for (int u = 0; u < 4; u++){
            int idx = t + 128*u; int row = idx >> 3, q4 = idx & 7;
            *(uint4*)&Ws_h[row*72 + q4*8] = *(const uint4*)&Wth[(size_t)row*DIN + c16*64 + q4*8];
            *(uint4*)&Ws_l[row*72 + q4*8] = *(const uint4*)&Wtl[(size_t)row*DIN + c16*64 + q4*8];
        }
        __syncthreads();
        #pragma unroll
        for (int ks = 0; ks < 4; ks++){
            u32 ah[2][4], al[2][4];
            #pragma unroll
            for (int grp = 0; grp < 2; grp++){
                ldsm4(ah[grp][0],ah[grp][1],ah[grp][2],ah[grp][3], a_h[grp] + ks*32);
                ldsm4(al[grp][0],al[grp][1],al[grp][2],al[grp][3], a_l[grp] + ks*32);
            }
            #pragma unroll
            for (int ph = 0; ph < 2; ph++){
                u32 b0h[4], b1h[4], b0l[4], b1l[4];
                ldsm4(b0h[0],b0h[1],b0h[2],b0h[3], b_h + (2*ph)*2304   + ks*32);
                ldsm4(b1h[0],b1h[1],b1h[2],b1h[3], b_h + (2*ph+1)*2304 + ks*32);
                ldsm4(b0l[0],b0l[1],b0l[2],b0l[3], b_l + (2*ph)*2304   + ks*32);
                ldsm4(b1l[0],b1l[1],b1l[2],b1l[3], b_l + (2*ph+1)*2304 + ks*32);
                #pragma unroll
                for (int grp = 0; grp < 2; grp++){
                    mma_bf(acc[grp][4*ph+0], ah[grp], b0h[0], b0h[1]);
                    mma_bf(acc[grp][4*ph+1], ah[grp], b0h[2], b0h[3]);
                    mma_bf(acc[grp][4*ph+2], ah[grp], b1h[0], b1h[1]);
                    mma_bf(acc[grp][4*ph+3], ah[grp], b1h[2], b1h[3]);
                    mma_bf(acc[grp][4*ph+0], ah[grp], b0l[0], b0l[1]);
                    mma_bf(acc[grp][4*ph+1], ah[grp], b0l[2], b0l[3]);
                    mma_bf(acc[grp][4*ph+2], ah[grp], b1l[0], b1l[1]);
                    mma_bf(acc[grp][4*ph+3], ah[grp], b1l[2], b1l[3]);
                    mma_bf(acc[grp][4*ph+0], al[grp], b0h[0], b0h[1]);
                    mma_bf(acc[grp][4*ph+1], al[grp], b0h[2], b0h[3]);
                    mma_bf(acc[grp][4*ph+2], al[grp], b1h[0], b1h[1]);
                    mma_bf(acc[grp][4*ph+3], al[grp], b1h[2], b1h[3]);
                }
            }
        }
    }

    const int g = lane >> 2, t2 = lane & 3;
    #pragma unroll
    for (int grp = 0; grp < 2; grp++){
        const int r0 = m0 + 32*warp + 16*grp + g, r1 = r0 + 8;
        #pragma unroll
        for (int nb = 0; nb < 8; nb++){
            int col = nb*8 + t2*2;
            float b0v = bias[col], b1v = bias[col+1];
            float v00 = fmaxf(acc[grp][nb][0] + b0v, 0.f) * oscale;
            float v01 = fmaxf(acc[grp][nb][1] + b1v, 0.f) * oscale;
            float v10 = fmaxf(acc[grp][nb][2] + b0v, 0.f) * oscale;
            float v11 = fmaxf(acc[grp][nb][3] + b1v, 0.f) * oscale;
            if (w == 2){
                storeV(r0, col, v00); storeV(r0, col+1, v01);
                storeV(r1, col, v10); storeV(r1, col+1, v11);
            } else {
                u16* Oh = (w==0) ? g_Qh : g_Kh;
                u16* Ol = (w==0) ? g_Ql : g_Kl;
                u32 h = packbf(v00, v01);
                u32 lo = packbf(v00 - bflo(h), v01 - bfhi(h));
                *(u32*)&Oh[(size_t)r0*DH + col] = h; *(u32*)&Ol[(size_t)r0*DH + col] = lo;
                h = packbf(v10, v11);
                lo = packbf(v10 - bflo(h), v11 - bfhi(h));
                *(u32*)&Oh[(size_t)r1*DH + col] = h; *(u32*)&Ol[(size_t)r1*DH + col] = lo;
            }
        }
    }
}

// ---------------- kernel: flash attention via HMMA -------------------------
// grid (SS/128, BB, NSPLIT), 128 threads. Bq=128 (4 warps x 32 rows), Bk=64.
// S in log2 domain; exp via ex2.approx. PV single product (P_hi*V_hi).
__global__ __launch_bounds__(128, 2) void attn_mma()
{
    extern __shared__ u16 smu[];
    u16* Qh = smu;                 // 128*72
    u16* Ql = Qh + 128*72;
    u16* Kh = Ql + 128*72;         // 64*72 each below
    u16* Kl = Kh + 64*72;
    u16* Vh = Kl + 64*72;

    const int t = threadIdx.x, lane = t & 31, wid = t >> 5;
    const int b = blockIdx.y, z = blockIdx.z;
    const int q0 = blockIdx.x * 128;
    const int base = b * SS;

    // stage Q (128 rows, hi+lo)
    #pragma unroll
    for (int u = 0; u < 8; u++){
        int idx = t + 128*u; int row = idx >> 3, q4 = idx & 7;
        *(uint4*)&Qh[row*72 + q4*8] = *(const uint4*)&g_Qh[(size_t)(base+q0+row)*DH + q4*8];
        *(uint4*)&Ql[row*72 + q4*8] = *(const uint4*)&g_Ql[(size_t)(base+q0+row)*DH + q4*8];
    }

    u32 qh_a[2], ql_a[2];
    #pragma unroll
    for (int grp = 0; grp < 2; grp++){
        u32 aoff = ((u32)(32*wid + 16*grp + (lane&15))*72 + ((lane>>4)<<3)) * 2;
        qh_a[grp] = smaddr(Qh) + aoff;
        ql_a[grp] = smaddr(Ql) + aoff;
    }
    const u32 boff = (((lane&7) + ((lane>>4)<<3))*72 + (((lane>>3)&1)<<3)) * 2;
    const u32 kh_b = smaddr(Kh) + boff, kl_b = smaddr(Kl) + boff;
    const u32 vh_b = smaddr(Vh) + boff;

    float o[2][8][4] = {};
    float mr[2][2] = {{-3e38f,-3e38f},{-3e38f,-3e38f}};
    float lr[2][2] = {{0.f,0.f},{0.f,0.f}};

    for (int it = 0; it < KT_PER; it++){
        const int k0 = (z*KT_PER + it) * 64;
        __syncthreads();
        #pragma unroll
        for (int u = 0; u < 4; u++){
            int idx = t + 128*u; int row = idx >> 3, q4 = idx & 7;
            *(uint4*)&Kh[row*72 + q4*8] = *(const uint4*)&g_Kh[(size_t)(base+k0+row)*DH + q4*8];
            *(uint4*)&Kl[row*72 + q4*8] = *(const uint4*)&g_Kl[(size_t)(base+k0+row)*DH + q4*8];
        }
        #pragma unroll
        for (int u = 0; u < 2; u++){
            int idx = t + 128*u; int row = idx >> 2, q4 = (idx & 3) * 2;
            *(uint4*)&Vh[row*72 + q4*8] =
                *(const uint4*)&g_Vh[(size_t)(b*64+row)*SS + k0 + q4*8];
            *(uint4*)&Vh[row*72 + q4*8 + 8] =
                *(const uint4*)&g_Vh[(size_t)(b*64+row)*SS + k0 + q4*8 + 8];
        }
        __syncthreads();

        // ---- S = Q @ K^T (full 3-product split) ----
        float s[2][8][4] = {};
        #pragma unroll
        for (int ks = 0; ks < 4; ks++){
            u32 ah[2][4], al[2][4];
            #pragma unroll
            for (int grp = 0; grp < 2; grp++){
                ldsm4(ah[grp][0],ah[grp][1],ah[grp][2],ah[grp][3], qh_a[grp] + ks*32);
                ldsm4(al[grp][0],al[grp][1],al[grp][2],al[grp][3], ql_a[grp] + ks*32);
            }
            #pragma unroll
            for (int ph = 0; ph < 2; ph++){
                u32 b0h[4], b1h[4], b0l[4], b1l[4];
                ldsm4(b0h[0],b0h[1],b0h[2],b0h[3], kh_b + (2*ph)*2304   + ks*32);
                ldsm4(b1h[0],b1h[1],b1h[2],b1h[3], kh_b + (2*ph+1)*2304 + ks*32);
                ldsm4(b0l[0],b0l[1],b0l[2],b0l[3], kl_b + (2*ph)*2304   + ks*32);
                ldsm4(b1l[0],b1l[1],b1l[2],b1l[3], kl_b + (2*ph+1)*2304 + ks*32);
                #pragma unroll
                for (int grp = 0; grp < 2; grp++){
                    mma_bf(s[grp][4*ph+0], ah[grp], b0h[0], b0h[1]);
                    mma_bf(s[grp][4*ph+1], ah[grp], b0h[2], b0h[3]);
                    mma_bf(s[grp][4*ph+2], ah[grp], b1h[0], b1h[1]);
                    mma_bf(s[grp][4*ph+3], ah[grp], b1h[2], b1h[3]);
                    mma_bf(s[grp][4*ph+0], ah[grp], b0l[0], b0l[1]);
                    mma_bf(s[grp][4*ph+1], ah[grp], b0l[2], b0l[3]);
                    mma_bf(s[grp][4*ph+2], ah[grp], b1l[0], b1l[1]);
                    mma_bf(s[grp][4*ph+3], ah[grp], b1l[2], b1l[3]);
                    mma_bf(s[grp][4*ph+0], al[grp], b0h[0], b0h[1]);
                    mma_bf(s[grp][4*ph+1], al[grp], b0h[2], b0h[3]);
                    mma_bf(s[grp][4*ph+2], al[grp], b1h[0], b1h[1]);
                    mma_bf(s[grp][4*ph+3], al[grp], b1h[2], b1h[3]);
                }
            }
        }

        // ---- online softmax in log2 domain (4 rows/thread) ----
        #pragma unroll
        for (int grp = 0; grp < 2; grp++){
            #pragma unroll
            for (int ri = 0; ri < 2; ri++){
                float mi = -3e38f;
                #pragma unroll
                for (int nb = 0; nb < 8; nb++)
                    mi = fmaxf(mi, fmaxf(s[grp][nb][2*ri], s[grp][nb][2*ri+1]));
                mi = fmaxf(mi, __shfl_xor_sync(0xffffffffu, mi, 1));
                mi = fmaxf(mi, __shfl_xor_sync(0xffffffffu, mi, 2));
                float mold = mr[grp][ri];
                float mnew = fmaxf(mold, mi);
                float sc = ex2f(mold - mnew);
                mr[grp][ri] = mnew;
                float li = 0.f;
                #pragma unroll
                for (int nb = 0; nb < 8; nb++){
                    float e0 = ex2f(s[grp][nb][2*ri]   - mnew);
                    float e1 = ex2f(s[grp][nb][2*ri+1] - mnew);
                    s[grp][nb][2*ri] = e0; s[grp][nb][2*ri+1] = e1;
                    li += e0 + e1;
                }
                li += __shfl_xor_sync(0xffffffffu, li, 1);
                li += __shfl_xor_sync(0xffffffffu, li, 2);
                lr[grp][ri] = lr[grp][ri]*sc + li;
                // warp-uniform skip: only rescale O if any lane's max moved
                if (__any_sync(0xffffffffu, sc != 1.0f)){
                    #pragma unroll
                    for (int nb = 0; nb < 8; nb++){
                        o[grp][nb][2*ri]   *= sc;
                        o[grp][nb][2*ri+1] *= sc;
                    }
                }
            }
        }

        // ---- P convert (hi only) + O += P @ V (single product) ----
        #pragma unroll
        for (int ks = 0; ks < 4; ks++){
            u32 ph4[2][4];
            #pragma unroll
            for (int grp = 0; grp < 2; grp++){
                ph4[grp][0] = packbf(s[grp][2*ks][0],   s[grp][2*ks][1]);
                ph4[grp][1] = packbf(s[grp][2*ks][2],   s[grp][2*ks][3]);
                ph4[grp][2] = packbf(s[grp][2*ks+1][0], s[grp][2*ks+1][1]);
                ph4[grp][3] = packbf(s[grp][2*ks+1][2], s[grp][2*ks+1][3]);
            }
            #pragma unroll
            for (int ph = 0; ph < 2; ph++){
                u32 v0h[4], v1h[4];
                ldsm4(v0h[0],v0h[1],v0h[2],v0h[3], vh_b + (2*ph)*2304   + ks*32);
                ldsm4(v1h[0],v1h[1],v1h[2],v1h[3], vh_b + (2*ph+1)*2304 + ks*32);
                #pragma unroll
                for (int grp = 0; grp < 2; grp++){
                    mma_bf(o[grp][4*ph+0], ph4[grp], v0h[0], v0h[1]);
                    mma_bf(o[grp][4*ph+1], ph4[grp], v0h[2], v0h[3]);
                    mma_bf(o[grp][4*ph+2], ph4[grp], v1h[0], v1h[1]);
                    mma_bf(o[grp][4*ph+3], ph4[grp], v1h[2], v1h[3]);
                }
            }
        }
    }

    // ---- write unnormalized partials + stats ----
    const int g = lane >> 2, t2 = lane & 3;
    #pragma unroll
    for (int grp = 0; grp < 2; grp++){
        const int r0 = base + q0 + 32*wid + 16*grp + g, r1 = r0 + 8;
        #pragma unroll
        for (int nb = 0; nb < 8; nb++){
            *(float2*)&g_Op[z][(size_t)r0*DH + nb*8 + t2*2] = make_float2(o[grp][nb][0], o[grp][nb][1]);
            *(float2*)&g_Op[z][(size_t)r1*DH + nb*8 + t2*2] = make_float2(o[grp][nb][2], o[grp][nb][3]);
        }
        if (t2 == 0){
            g_m[z][r0] = mr[grp][0]; g_l[z][r0] = lr[grp][0];
            g_m[z][r1] = mr[grp][1]; g_l[z][r1] = lr[grp][1];
        }
    }
}

// ---------------- kernel: flash split combine + mask (log2 domain) ---------
__global__ __launch_bounds__(256) void combine(const float* __restrict__ mask,
                                               float* __restrict__ out){
    int idx = blockIdx.x*256 + threadIdx.x;   // row*16 + dquad
    int row = idx >> 4, dq = idx & 15;
    float mm = -3e38f;
    #pragma unroll
    for (int z = 0; z < NSPLIT; z++) mm = fmaxf(mm, g_m[z][row]);
    float den = 0.f;
    float4 r = make_float4(0.f, 0.f, 0.f, 0.f);
    #pragma unroll
    for (int z = 0; z < NSPLIT; z++){
        float wz = ex2f(g_m[z][row] - mm);
        den += wz * g_l[z][row];
        float4 a = *(const float4*)&g_Op[z][(size_t)row*DH + dq*4];
        r.x += a.x*wz; r.y += a.y*wz; r.z += a.z*wz; r.w += a.w*wz;
    }
    float f = mask[row] / den;
    r.x *= f; r.y *= f; r.z *= f; r.w *= f;
    *(float4*)&out[(size_t)row*DH + dq*4] = r;
}

// ---------------------------------------------------------------------------
extern "C" void kernel_launch(void* const* d_in, const int* in_sizes, int n_in,
                              void* d_out, int out_size)
{
    const float* X    = (const float*)d_in[0];
    const float* mask = (const float*)d_in[1];
    const float* Wq   = (const float*)d_in[2];
    const float* bq   = (const float*)d_in[3];
    const float* Wk   = (const float*)d_in[4];
    const float* bk   = (const float*)d_in[5];
    const float* Wv   = (const float*)d_in[6];
    const float* bv   = (const float*)d_in[7];

    // attn smem: Qh+Ql (128x72) + Kh,Kl,Vh (64x72), u16 -> 64512 B
    const int smem_attn = (2*128*72 + 3*64*72) * (int)sizeof(u16);
    cudaFuncSetAttribute(attn_mma,
                         cudaFuncAttributeMaxDynamicSharedMemorySize, smem_attn);
    // qkv smem: Xh+Xl (128x72) + Wh,Wl (64x72), u16 -> 55296 B
    const int smem_qkv = (2*128*72 + 2*64*72) * (int)sizeof(u16);
    cudaFuncSetAttribute(qkv_mma,
                         cudaFuncAttributeMaxDynamicSharedMemorySize, smem_qkv);

    cvt_w<<<3*DH*DIN/256, 256>>>(Wq, Wk, Wv);
    qkv_mma<<<dim3(MROWS/128, 3), 128, smem_qkv>>>(X, bq, bk, bv);
    attn_mma<<<dim3(SS/128, BB, NSPLIT), 128, smem_attn>>>();
    combine<<<MROWS*DH/4/256, 256>>>(mask, (float*)d_out);
}

// round 16
// speedup vs baseline: 1.1582x; 1.0274x over previous
#include <cuda_runtime.h>

typedef unsigned int u32;
typedef unsigned short u16;

#define BB 4
#define SS 4096
#define DIN 1024
#define DH 64
#define MROWS (BB*SS)
#define NSPLIT 8
#define KTS (SS/64)
#define KT_PER (KTS/NSPLIT)
#define LOG2E 1.4426950408889634f

// ---------------- scratch (static device memory; no allocations) ----------
__device__ u16 g_Wth[3][DH*DIN], g_Wtl[3][DH*DIN];         // W^T split bf16 [out][din]
__device__ u16 g_Qh[MROWS*DH], g_Ql[MROWS*DH];             // [row][d], pre-scaled by log2e
__device__ u16 g_Kh[MROWS*DH], g_Kl[MROWS*DH];             // [row][d]
__device__ u16 g_Vh[MROWS*DH];                             // transposed [b][d][s], hi only
__device__ float g_Op[NSPLIT][MROWS*DH];                   // unnormalized partial O
__device__ float g_m[NSPLIT][MROWS];                       // running max (log2 domain)
__device__ float g_l[NSPLIT][MROWS];

// ---------------- helpers --------------------------------------------------
__device__ __forceinline__ u32 packbf(float lo, float hi){
    u32 r; asm("cvt.rn.bf16x2.f32 %0, %1, %2;" : "=r"(r) : "f"(hi), "f"(lo)); return r;
}
__device__ __forceinline__ float bflo(u32 p){ return __uint_as_float(p << 16); }
__device__ __forceinline__ float bfhi(u32 p){ return __uint_as_float(p & 0xffff0000u); }
__device__ __forceinline__ u32 smaddr(const void* p){ return (u32)__cvta_generic_to_shared(p); }
__device__ __forceinline__ float ex2f(float x){
    float r; asm("ex2.approx.f32 %0, %1;" : "=f"(r) : "f"(x)); return r;
}

__device__ __forceinline__ void ldsm4(u32& r0,u32& r1,u32& r2,u32& r3, u32 a){
    asm volatile("ldmatrix.sync.aligned.m8n8.x4.shared.b16 {%0,%1,%2,%3}, [%4];"
        : "=r"(r0),"=r"(r1),"=r"(r2),"=r"(r3) : "r"(a));
}
__device__ __forceinline__ void mma_bf(float* c, const u32* a, u32 b0, u32 b1){
    asm volatile("mma.sync.aligned.m16n8k16.row.col.f32.bf16.bf16.f32 "
        "{%0,%1,%2,%3},{%4,%5,%6,%7},{%8,%9},{%0,%1,%2,%3};"
        : "+f"(c[0]),"+f"(c[1]),"+f"(c[2]),"+f"(c[3])
        : "r"(a[0]),"r"(a[1]),"r"(a[2]),"r"(a[3]),"r"(b0),"r"(b1));
}

// ---------------- kernel: convert+transpose weights ------------------------
__global__ __launch_bounds__(256) void cvt_w(const float* __restrict__ Wq,
                                             const float* __restrict__ Wk,
                                             const float* __restrict__ Wv){
    int id = blockIdx.x*256 + threadIdx.x;
    int w = id >> 16; int r = id & 65535;
    int n = r >> 10, k = r & 1023;
    const float* W = (w==0) ? Wq : (w==1) ? Wk : Wv;
    float x = W[k*DH + n];
    u32 p = packbf(x, 0.f);
    u32 q = packbf(x - bflo(p), 0.f);
    g_Wth[w][n*DIN + k] = (u16)(p & 0xffff);
    g_Wtl[w][n*DIN + k] = (u16)(q & 0xffff);
}

__device__ __forceinline__ void storeV(int r, int c, float v){
    int bb = r >> 12, s = r & 4095;
    u32 p = packbf(v, 0.f);
    g_Vh[(size_t)(bb*64 + c)*SS + s] = (u16)(p & 0xffff);
}

// ---------------- kernel: QKV projection via HMMA, fused X split -----------
// grid (MROWS/128, 3), 128 threads. 4 warps x 2 x m16 groups = 128 rows/CTA.
// Q output is pre-scaled by log2e so attention S is in log2 domain.
__global__ __launch_bounds__(128, 3) void qkv_mma(
    const float* __restrict__ X,
    const float* __restrict__ bq, const float* __restrict__ bk,
    const float* __restrict__ bv)
{
    extern __shared__ u16 smq[];
    u16* Xs_h = smq;               // 128*72
    u16* Xs_l = Xs_h + 128*72;
    u16* Ws_h = Xs_l + 128*72;     // 64*72
    u16* Ws_l = Ws_h + 64*72;

    const int t = threadIdx.x, lane = t & 31, warp = t >> 5;
    const int w = blockIdx.y;
    const int m0 = blockIdx.x * 128;
    const u16* Wth = g_Wth[w]; const u16* Wtl = g_Wtl[w];
    const float* bias = (w==0) ? bq : (w==1) ? bk : bv;
    const float oscale = (w==0) ? LOG2E : 1.0f;

    u32 a_h[2], a_l[2];
    #pragma unroll
    for (int grp = 0; grp < 2; grp++){
        u32 aoff = ((u32)(32*warp + 16*grp + (lane&15))*72 + ((lane>>4)<<3)) * 2;
        a_h[grp] = smaddr(Xs_h) + aoff;
        a_l[grp] = smaddr(Xs_l) + aoff;
    }
    const u32 boff = (((lane&7) + ((lane>>4)<<3))*72 + (((lane>>3)&1)<<3)) * 2;
    const u32 b_h = smaddr(Ws_h) + boff, b_l = smaddr(Ws_l) + boff;

    float acc[2][8][4] = {};
    for (int c16 = 0; c16 < 16; c16++){
        __syncthreads();
        #pragma unroll
        for (int u = 0; u < 8; u++){
            int idx = t + 128*u; int row = idx >> 3, q4 = idx & 7;
            const float* xp = &X[(size_t)(m0+row)*DIN + c16*64 + q4*8];
            float4 v0 = *(const float4*)xp;
            float4 v1 = *(const float4*)(xp + 4);
            u32 h01 = packbf(v0.x, v0.y), h23 = packbf(v0.z, v0.w);
            u32 h45 = packbf(v1.x, v1.y), h67 = packbf(v1.z, v1.w);
            u32 l01 = packbf(v0.x - bflo(h01), v0.y - bfhi(h01));
            u32 l23 = packbf(v0.z - bflo(h23), v0.w - bfhi(h23));
            u32 l45 = packbf(v1.x - bflo(h45), v1.y - bfhi(h45));
            u32 l67 = packbf(v1.z - bflo(h67), v1.w - bfhi(h67));
            *(uint4*)&Xs_h[row*72 + q4*8] = make_uint4(h01, h23, h45, h67);
            *(uint4*)&Xs_l[row*72 + q4*8] = make_uint4(l01, l23, l45, l67);
        }
        #pragma unroll
        for (int u = 0; u < 4; u++){
            int idx = t + 128*u; int row = idx >> 3, q4 = idx & 7;
            *(uint4*)&Ws_h[row*72 + q4*8] = *(const uint4*)&Wth[(size_t)row*DIN + c16*64 + q4*8];
            *(uint4*)&Ws_l[row*72 + q4*8] = *(const uint4*)&Wtl[(size_t)row*DIN + c16*64 + q4*8];
        }
        __syncthreads();
        #pragma unroll
        for (int ks = 0; ks < 4; ks++){
            u32 ah[2][4], al[2][4];
            #pragma unroll
            for (int grp = 0; grp < 2; grp++){
                ldsm4(ah[grp][0],ah[grp][1],ah[grp][2],ah[grp][3], a_h[grp] + ks*32);
                ldsm4(al[grp][0],al[grp][1],al[grp][2],al[grp][3], a_l[grp] + ks*32);
            }
            #pragma unroll
            for (int ph = 0; ph < 2; ph++){
                u32 b0h[4], b1h[4], b0l[4], b1l[4];
                ldsm4(b0h[0],b0h[1],b0h[2],b0h[3], b_h + (2*ph)*2304   + ks*32);
                ldsm4(b1h[0],b1h[1],b1h[2],b1h[3], b_h + (2*ph+1)*2304 + ks*32);
                ldsm4(b0l[0],b0l[1],b0l[2],b0l[3], b_l + (2*ph)*2304   + ks*32);
                ldsm4(b1l[0],b1l[1],b1l[2],b1l[3], b_l + (2*ph+1)*2304 + ks*32);
                #pragma unroll
                for (int grp = 0; grp < 2; grp++){
                    mma_bf(acc[grp][4*ph+0], ah[grp], b0h[0], b0h[1]);
                    mma_bf(acc[grp][4*ph+1], ah[grp], b0h[2], b0h[3]);
                    mma_bf(acc[grp][4*ph+2], ah[grp], b1h[0], b1h[1]);
                    mma_bf(acc[grp][4*ph+3], ah[grp], b1h[2], b1h[3]);
                    mma_bf(acc[grp][4*ph+0], ah[grp], b0l[0], b0l[1]);
                    mma_bf(acc[grp][4*ph+1], ah[grp], b0l[2], b0l[3]);
                    mma_bf(acc[grp][4*ph+2], ah[grp], b1l[0], b1l[1]);
                    mma_bf(acc[grp][4*ph+3], ah[grp], b1l[2], b1l[3]);
                    mma_bf(acc[grp][4*ph+0], al[grp], b0h[0], b0h[1]);
                    mma_bf(acc[grp][4*ph+1], al[grp], b0h[2], b0h[3]);
                    mma_bf(acc[grp][4*ph+2], al[grp], b1h[0], b1h[1]);
                    mma_bf(acc[grp][4*ph+3], al[grp], b1h[2], b1h[3]);
                }
            }
        }
    }

    const int g = lane >> 2, t2 = lane & 3;
    #pragma unroll
    for (int grp = 0; grp < 2; grp++){
        const int r0 = m0 + 32*warp + 16*grp + g, r1 = r0 + 8;
        #pragma unroll
        for (int nb = 0; nb < 8; nb++){
            int col = nb*8 + t2*2;
            float b0v = bias[col], b1v = bias[col+1];
            float v00 = fmaxf(acc[grp][nb][0] + b0v, 0.f) * oscale;
            float v01 = fmaxf(acc[grp][nb][1] + b1v, 0.f) * oscale;
            float v10 = fmaxf(acc[grp][nb][2] + b0v, 0.f) * oscale;
            float v11 = fmaxf(acc[grp][nb][3] + b1v, 0.f) * oscale;
            if (w == 2){
                storeV(r0, col, v00); storeV(r0, col+1, v01);
                storeV(r1, col, v10); storeV(r1, col+1, v11);
            } else {
                u16* Oh = (w==0) ? g_Qh : g_Kh;
                u16* Ol = (w==0) ? g_Ql : g_Kl;
                u32 h = packbf(v00, v01);
                u32 lo = packbf(v00 - bflo(h), v01 - bfhi(h));
                *(u32*)&Oh[(size_t)r0*DH + col] = h; *(u32*)&Ol[(size_t)r0*DH + col] = lo;
                h = packbf(v10, v11);
                lo = packbf(v10 - bflo(h), v11 - bfhi(h));
                *(u32*)&Oh[(size_t)r1*DH + col] = h; *(u32*)&Ol[(size_t)r1*DH + col] = lo;
            }
        }
    }
}

// ---------------- kernel: flash attention via HMMA, 8 warps x M=16 ---------
// grid (SS/128, BB, NSPLIT), 256 threads. Bq=128 (8 warps x 16 rows), Bk=64.
// 2 CTAs/SM -> 16 warps/SM. S in log2 domain; PV single product.
__global__ __launch_bounds__(256, 2) void attn_mma()
{
    extern __shared__ u16 smu[];
    u16* Qh = smu;                 // 128*72
    u16* Ql = Qh + 128*72;
    u16* Kh = Ql + 128*72;         // 64*72 each below
    u16* Kl = Kh + 64*72;
    u16* Vh = Kl + 64*72;

    const int t = threadIdx.x, lane = t & 31, wid = t >> 5;
    const int b = blockIdx.y, z = blockIdx.z;
    const int q0 = blockIdx.x * 128;
    const int base = b * SS;

    // stage Q (128 rows, hi+lo): 2048 uint4 over 256 threads
    #pragma unroll
    for (int u = 0; u < 4; u++){
        int idx = t + 256*u; int row = idx >> 3, q4 = idx & 7;
        *(uint4*)&Qh[row*72 + q4*8] = *(const uint4*)&g_Qh[(size_t)(base+q0+row)*DH + q4*8];
        *(uint4*)&Ql[row*72 + q4*8] = *(const uint4*)&g_Ql[(size_t)(base+q0+row)*DH + q4*8];
    }

    const u32 aoff = ((u32)(16*wid + (lane&15))*72 + ((lane>>4)<<3)) * 2;
    const u32 qh_a = smaddr(Qh) + aoff, ql_a = smaddr(Ql) + aoff;
    const u32 boff = (((lane&7) + ((lane>>4)<<3))*72 + (((lane>>3)&1)<<3)) * 2;
    const u32 kh_b = smaddr(Kh) + boff, kl_b = smaddr(Kl) + boff;
    const u32 vh_b = smaddr(Vh) + boff;

    float o[8][4] = {};
    float mr[2] = {-3e38f, -3e38f};
    float lr[2] = {0.f, 0.f};

    for (int it = 0; it < KT_PER; it++){
        const int k0 = (z*KT_PER + it) * 64;
        __syncthreads();
        // stage K hi+lo (1024 uint4) and V hi (512 uint4) over 256 threads
        #pragma unroll
        for (int u = 0; u < 2; u++){
            int idx = t + 256*u; int row = idx >> 3, q4 = idx & 7;
            *(uint4*)&Kh[row*72 + q4*8] = *(const uint4*)&g_Kh[(size_t)(base+k0+row)*DH + q4*8];
            *(uint4*)&Kl[row*72 + q4*8] = *(const uint4*)&g_Kl[(size_t)(base+k0+row)*DH + q4*8];
        }
        {
            int row = t >> 2, q4 = (t & 3) * 2;
            const u16* vsrc = &g_Vh[(size_t)(b*64+row)*SS + k0 + q4*8];
            *(uint4*)&Vh[row*72 + q4*8]     = *(const uint4*)vsrc;
            *(uint4*)&Vh[row*72 + q4*8 + 8] = *(const uint4*)(vsrc + 8);
        }
        __syncthreads();

        // ---- S = Q @ K^T (full 3-product split), M=16/warp ----
        float s[8][4] = {};
        #pragma unroll
        for (int ks = 0; ks < 4; ks++){
            u32 ah[4], al[4];
            ldsm4(ah[0],ah[1],ah[2],ah[3], qh_a + ks*32);
            ldsm4(al[0],al[1],al[2],al[3], ql_a + ks*32);
            #pragma unroll
            for (int ph = 0; ph < 2; ph++){
                u32 b0h[4], b1h[4], b0l[4], b1l[4];
                ldsm4(b0h[0],b0h[1],b0h[2],b0h[3], kh_b + (2*ph)*2304   + ks*32);
                ldsm4(b1h[0],b1h[1],b1h[2],b1h[3], kh_b + (2*ph+1)*2304 + ks*32);
                ldsm4(b0l[0],b0l[1],b0l[2],b0l[3], kl_b + (2*ph)*2304   + ks*32);
                ldsm4(b1l[0],b1l[1],b1l[2],b1l[3], kl_b + (2*ph+1)*2304 + ks*32);
                mma_bf(s[4*ph+0], ah, b0h[0], b0h[1]);
                mma_bf(s[4*ph+1], ah, b0h[2], b0h[3]);
                mma_bf(s[4*ph+2], ah, b1h[0], b1h[1]);
                mma_bf(s[4*ph+3], ah, b1h[2], b1h[3]);
                mma_bf(s[4*ph+0], ah, b0l[0], b0l[1]);
                mma_bf(s[4*ph+1], ah, b0l[2], b0l[3]);
                mma_bf(s[4*ph+2], ah, b1l[0], b1l[1]);
                mma_bf(s[4*ph+3], ah, b1l[2], b1l[3]);
                mma_bf(s[4*ph+0], al, b0h[0], b0h[1]);
                mma_bf(s[4*ph+1], al, b0h[2], b0h[3]);
                mma_bf(s[4*ph+2], al, b1h[0], b1h[1]);
                mma_bf(s[4*ph+3], al, b1h[2], b1h[3]);
            }
        }

        // ---- online softmax in log2 domain (2 rows/thread: g, g+8) ----
        #pragma unroll
        for (int ri = 0; ri < 2; ri++){
            float mi = -3e38f;
            #pragma unroll
            for (int nb = 0; nb < 8; nb++)
                mi = fmaxf(mi, fmaxf(s[nb][2*ri], s[nb][2*ri+1]));
            mi = fmaxf(mi, __shfl_xor_sync(0xffffffffu, mi, 1));
            mi = fmaxf(mi, __shfl_xor_sync(0xffffffffu, mi, 2));
            float mold = mr[ri];
            float mnew = fmaxf(mold, mi);
            float sc = ex2f(mold - mnew);
            mr[ri] = mnew;
            float li = 0.f;
            #pragma unroll
            for (int nb = 0; nb < 8; nb++){
                float e0 = ex2f(s[nb][2*ri]   - mnew);
                float e1 = ex2f(s[nb][2*ri+1] - mnew);
                s[nb][2*ri] = e0; s[nb][2*ri+1] = e1;
                li += e0 + e1;
            }
            li += __shfl_xor_sync(0xffffffffu, li, 1);
            li += __shfl_xor_sync(0xffffffffu, li, 2);
            lr[ri] = lr[ri]*sc + li;
            if (__any_sync(0xffffffffu, sc != 1.0f)){
                #pragma unroll
                for (int nb = 0; nb < 8; nb++){
                    o[nb][2*ri]   *= sc;
                    o[nb][2*ri+1] *= sc;
                }
            }
        }

        // ---- P convert (hi only) + O += P @ V (single product) ----
        #pragma unroll
        for (int ks = 0; ks < 4; ks++){
            u32 ph4[4];
            ph4[0] = packbf(s[2*ks][0],   s[2*ks][1]);
            ph4[1] = packbf(s[2*ks][2],   s[2*ks][3]);
            ph4[2] = packbf(s[2*ks+1][0], s[2*ks+1][1]);
            ph4[3] = packbf(s[2*ks+1][2], s[2*ks+1][3]);
            #pragma unroll
            for (int ph = 0; ph < 2; ph++){
                u32 v0h[4], v1h[4];
                ldsm4(v0h[0],v0h[1],v0h[2],v0h[3], vh_b + (2*ph)*2304   + ks*32);
                ldsm4(v1h[0],v1h[1],v1h[2],v1h[3], vh_b + (2*ph+1)*2304 + ks*32);
                mma_bf(o[4*ph+0], ph4, v0h[0], v0h[1]);
                mma_bf(o[4*ph+1], ph4, v0h[2], v0h[3]);
                mma_bf(o[4*ph+2], ph4, v1h[0], v1h[1]);
                mma_bf(o[4*ph+3], ph4, v1h[2], v1h[3]);
            }
        }
    }

    // ---- write unnormalized partials + stats ----
    const int g = lane >> 2, t2 = lane & 3;
    const int r0 = base + q0 + 16*wid + g, r1 = r0 + 8;
    #pragma unroll
    for (int nb = 0; nb < 8; nb++){
        *(float2*)&g_Op[z][(size_t)r0*DH + nb*8 + t2*2] = make_float2(o[nb][0], o[nb][1]);
        *(float2*)&g_Op[z][(size_t)r1*DH + nb*8 + t2*2] = make_float2(o[nb][2], o[nb][3]);
    }
    if (t2 == 0){
        g_m[z][r0] = mr[0]; g_l[z][r0] = lr[0];
        g_m[z][r1] = mr[1]; g_l[z][r1] = lr[1];
    }
}

// ---------------- kernel: flash split combine + mask (log2 domain) ---------
__global__ __launch_bounds__(256) void combine(const float* __restrict__ mask,
                                               float* __restrict__ out){
    int idx = blockIdx.x*256 + threadIdx.x;   // row*16 + dquad
    int row = idx >> 4, dq = idx & 15;
    float mm = -3e38f;
    #pragma unroll
    for (int z = 0; z < NSPLIT; z++) mm = fmaxf(mm, g_m[z][row]);
    float den = 0.f;
    float4 r = make_float4(0.f, 0.f, 0.f, 0.f);
    #pragma unroll
    for (int z = 0; z < NSPLIT; z++){
        float wz = ex2f(g_m[z][row] - mm);
        den += wz * g_l[z][row];
        float4 a = *(const float4*)&g_Op[z][(size_t)row*DH + dq*4];
        r.x += a.x*wz; r.y += a.y*wz; r.z += a.z*wz; r.w += a.w*wz;
    }
    float f = mask[row] / den;
    r.x *= f; r.y *= f; r.z *= f; r.w *= f;
    *(float4*)&out[(size_t)row*DH + dq*4] = r;
}

// ---------------------------------------------------------------------------
extern "C" void kernel_launch(void* const* d_in, const int* in_sizes, int n_in,
                              void* d_out, int out_size)
{
    const float* X    = (const float*)d_in[0];
    const float* mask = (const float*)d_in[1];
    const float* Wq   = (const float*)d_in[2];
    const float* bq   = (const float*)d_in[3];
    const float* Wk   = (const float*)d_in[4];
    const float* bk   = (const float*)d_in[5];
    const float* Wv   = (const float*)d_in[6];
    const float* bv   = (const float*)d_in[7];

    // attn smem: Qh+Ql (128x72) + Kh,Kl,Vh (64x72), u16 -> 64512 B
    const int smem_attn = (2*128*72 + 3*64*72) * (int)sizeof(u16);
    cudaFuncSetAttribute(attn_mma,
                         cudaFuncAttributeMaxDynamicSharedMemorySize, smem_attn);
    // qkv smem: Xh+Xl (128x72) + Wh,Wl (64x72), u16 -> 55296 B
    const int smem_qkv = (2*128*72 + 2*64*72) * (int)sizeof(u16);
    cudaFuncSetAttribute(qkv_mma,
                         cudaFuncAttributeMaxDynamicSharedMemorySize, smem_qkv);

    cvt_w<<<3*DH*DIN/256, 256>>>(Wq, Wk, Wv);
    qkv_mma<<<dim3(MROWS/128, 3), 128, smem_qkv>>>(X, bq, bk, bv);
    attn_mma<<<dim3(SS/128, BB, NSPLIT), 256, smem_attn>>>();
    combine<<<MROWS*DH/4/256, 256>>>(mask, (float*)d_out);
}